// round 15
// baseline (speedup 1.0000x reference)
#include <cuda_runtime.h>
#include <cstddef>

// ---------------------------------------------------------------------------
// NCEAverageMultiview on GB300 — inverted-index formulation, 4-row stream,
// finalize folded into epilogue (flag handshake).
//
// d_out (fp32): out_v1 [B*KP1] | out_v2 [B*KP1] | new_mem_v1 [N*D] | new_mem_v2 [N*D]
// ---------------------------------------------------------------------------

#define MAXN 1100000
#define CAP  8
#define OVF_CAP 65536

__device__ int    g_count[MAXN];
__device__ int    g_entries[MAXN * CAP];
__device__ int    g_ovf[OVF_CAP];
__device__ int    g_ovf_n;
__device__ double g_sum[2];
__device__ float  g_scale[2];
__device__ int    g_flag;

#define DOT4(p, a) ((p).x*(a).x + (p).y*(a).y + (p).z*(a).z + (p).w*(a).w)

__global__ void zero_kernel(int N) {
    const int n4 = N >> 2;
    const int i = blockIdx.x * blockDim.x + threadIdx.x;
    const int stride = gridDim.x * blockDim.x;
    int4* p = reinterpret_cast<int4*>(g_count);
    const int4 z = {0, 0, 0, 0};
    for (int j = i; j < n4; j += stride) p[j] = z;
    if (i == 0) {
        for (int j = n4 << 2; j < N; ++j) g_count[j] = 0;
        g_ovf_n = 0; g_sum[0] = 0.0; g_sum[1] = 0.0;
        g_flag = 0;
    }
}

// Build row -> (b,k) buckets. Entry encode: (b << 13) | k  (k <= 4096 < 8192).
__global__ void histogram_kernel(const int* __restrict__ y,
                                 const int* __restrict__ idx, int KP1) {
    const int k = blockIdx.x * blockDim.x + threadIdx.x;
    const int b = blockIdx.y;
    if (k >= KP1) return;
    const int i = (k == 0) ? y[b] : idx[(size_t)b * KP1 + k];
    const int e = (b << 13) | k;
    const int slot = atomicAdd(&g_count[i], 1);
    if (slot < CAP) {
        g_entries[(size_t)i * CAP + slot] = e;
    } else {
        const int p = atomicAdd(&g_ovf_n, 1);
        if (p < OVF_CAP) g_ovf[p] = e;
    }
}

// Streaming pass: warp handles 4 adjacent rows per iteration.
__global__ void __launch_bounds__(512) fused_kernel(
    const float* __restrict__ m1, const float* __restrict__ m2,
    const float* __restrict__ v1, const float* __restrict__ v2,
    float* __restrict__ om1, float* __restrict__ om2,
    float* __restrict__ out1, float* __restrict__ out2,
    int N, int KP1)
{
    __shared__ double sred1[16], sred2[16];
    const int lane = threadIdx.x & 31;
    const int warp = threadIdx.x >> 5;
    const int nWarps = gridDim.x * (blockDim.x >> 5);
    const int gw = blockIdx.x * (blockDim.x >> 5) + warp;
    const float invT = 1.0f / 0.07f;

    double acc1 = 0.0, acc2 = 0.0;
    const int Nquad = N & ~3;

    for (int r = gw * 4; r < Nquad; r += 4 * nWarps) {
        float4 x1[4], x2[4];
        #pragma unroll
        for (int q = 0; q < 4; ++q)
            x1[q] = __ldg(reinterpret_cast<const float4*>(m1 + (size_t)(r + q) * 128) + lane);
        #pragma unroll
        for (int q = 0; q < 4; ++q)
            x2[q] = __ldg(reinterpret_cast<const float4*>(m2 + (size_t)(r + q) * 128) + lane);

        const int4 cc = *reinterpret_cast<const int4*>(&g_count[r]);
        const int ev = g_entries[(size_t)r * CAP + lane];

        #pragma unroll
        for (int q = 0; q < 4; ++q)
            reinterpret_cast<float4*>(om1 + (size_t)(r + q) * 128)[lane] = x1[q];
        #pragma unroll
        for (int q = 0; q < 4; ++q)
            reinterpret_cast<float4*>(om2 + (size_t)(r + q) * 128)[lane] = x2[q];

        const int cArr[4] = { cc.x, cc.y, cc.z, cc.w };
        #pragma unroll
        for (int q = 0; q < 4; ++q) {
            int c = cArr[q];
            c = c < CAP ? c : CAP;
            for (int j = 0; j < c; ++j) {
                const int e = __shfl_sync(0xffffffffu, ev, q * CAP + j);
                const int b = e >> 13;
                const int k = e & 8191;
                const float4 a1 = __ldg(reinterpret_cast<const float4*>(v1 + (size_t)b * 128) + lane);
                const float4 a2 = __ldg(reinterpret_cast<const float4*>(v2 + (size_t)b * 128) + lane);
                // out_v1 = exp(<m2[r], v1[b]>/T);  out_v2 = exp(<m1[r], v2[b]>/T)
                float s1 = DOT4(x2[q], a1);
                float s2 = DOT4(x1[q], a2);
                #pragma unroll
                for (int o = 16; o; o >>= 1) {
                    s1 += __shfl_xor_sync(0xffffffffu, s1, o);
                    s2 += __shfl_xor_sync(0xffffffffu, s2, o);
                }
                if (lane == 0) {
                    const float e1 = __expf(s1 * invT);
                    const float e2 = __expf(s2 * invT);
                    out1[(size_t)b * KP1 + k] = e1;
                    out2[(size_t)b * KP1 + k] = e2;
                    acc1 += (double)e1;
                    acc2 += (double)e2;
                }
            }
        }
    }

    // tail rows (N not multiple of 4) handled by warp 0
    if (gw == 0) {
        for (int r = Nquad; r < N; ++r) {
            const float4 x1 = __ldg(reinterpret_cast<const float4*>(m1 + (size_t)r * 128) + lane);
            const float4 x2 = __ldg(reinterpret_cast<const float4*>(m2 + (size_t)r * 128) + lane);
            reinterpret_cast<float4*>(om1 + (size_t)r * 128)[lane] = x1;
            reinterpret_cast<float4*>(om2 + (size_t)r * 128)[lane] = x2;
            int c = g_count[r];
            const int ev = (lane < CAP) ? g_entries[(size_t)r * CAP + lane] : 0;
            c = c < CAP ? c : CAP;
            for (int j = 0; j < c; ++j) {
                const int e = __shfl_sync(0xffffffffu, ev, j);
                const int b = e >> 13;
                const int k = e & 8191;
                const float4 a1 = __ldg(reinterpret_cast<const float4*>(v1 + (size_t)b * 128) + lane);
                const float4 a2 = __ldg(reinterpret_cast<const float4*>(v2 + (size_t)b * 128) + lane);
                float s1 = DOT4(x2, a1);
                float s2 = DOT4(x1, a2);
                #pragma unroll
                for (int o = 16; o; o >>= 1) {
                    s1 += __shfl_xor_sync(0xffffffffu, s1, o);
                    s2 += __shfl_xor_sync(0xffffffffu, s2, o);
                }
                if (lane == 0) {
                    const float e1 = __expf(s1 * invT);
                    const float e2 = __expf(s2 * invT);
                    out1[(size_t)b * KP1 + k] = e1;
                    out2[(size_t)b * KP1 + k] = e2;
                    acc1 += (double)e1;
                    acc2 += (double)e2;
                }
            }
        }
    }

    if (lane == 0) { sred1[warp] = acc1; sred2[warp] = acc2; }
    __syncthreads();
    if (threadIdx.x == 0) {
        double t1 = 0.0, t2 = 0.0;
        #pragma unroll
        for (int j = 0; j < 16; ++j) { t1 += sred1[j]; t2 += sred2[j]; }
        atomicAdd(&g_sum[0], t1);
        atomicAdd(&g_sum[1], t2);
    }
}

// Single epilogue launch:
//  block 0                      : overflow fix-up + scale + flag release
//  blocks [1, normBlocks]       : preload outs -> spin on flag -> scale+store
//  blocks (normBlocks, ...]     : momentum scatter update (no flag dependency)
__global__ void __launch_bounds__(256) epilogue_kernel(
    float* __restrict__ out1, float* __restrict__ out2, int total, double nOutput,
    const float* __restrict__ v1, const float* __restrict__ v2,
    const float* __restrict__ m1, const float* __restrict__ m2,
    const int* __restrict__ y, const int* __restrict__ idx, int KP1,
    float* __restrict__ om1, float* __restrict__ om2,
    int B, int normBlocks)
{
    const float invT = 1.0f / 0.07f;

    if (blockIdx.x == 0) {
        // ---- overflow fix-up + scale (warp 0 only) ----
        if (threadIdx.x < 32) {
            const int lane = threadIdx.x;
            int n = g_ovf_n;
            n = n < OVF_CAP ? n : OVF_CAP;
            double acc1 = 0.0, acc2 = 0.0;
            for (int t = 0; t < n; ++t) {
                const int e = g_ovf[t];
                const int b = e >> 13;
                const int k = e & 8191;
                const int i = (k == 0) ? y[b] : idx[(size_t)b * KP1 + k];
                const float4 x1 = reinterpret_cast<const float4*>(m1 + (size_t)i * 128)[lane];
                const float4 x2 = reinterpret_cast<const float4*>(m2 + (size_t)i * 128)[lane];
                const float4 a1 = reinterpret_cast<const float4*>(v1 + (size_t)b * 128)[lane];
                const float4 a2 = reinterpret_cast<const float4*>(v2 + (size_t)b * 128)[lane];
                float s1 = DOT4(x2, a1);
                float s2 = DOT4(x1, a2);
                #pragma unroll
                for (int o = 16; o; o >>= 1) {
                    s1 += __shfl_xor_sync(0xffffffffu, s1, o);
                    s2 += __shfl_xor_sync(0xffffffffu, s2, o);
                }
                if (lane == 0) {
                    const float e1 = __expf(s1 * invT);
                    const float e2 = __expf(s2 * invT);
                    out1[(size_t)b * KP1 + k] = e1;
                    out2[(size_t)b * KP1 + k] = e2;
                    acc1 += (double)e1;
                    acc2 += (double)e2;
                }
            }
            if (lane == 0) {
                const double s1 = g_sum[0] + acc1;
                const double s2 = g_sum[1] + acc2;
                const double cnt = (double)total;
                g_scale[0] = (float)(cnt / (s1 * nOutput));
                g_scale[1] = (float)(cnt / (s2 * nOutput));
                __threadfence();
                atomicExch(&g_flag, 1);
            }
        }
        return;
    }

    if ((int)blockIdx.x <= normBlocks) {
        // ---- normalize: preload, then wait for scale ----
        const int n4 = total >> 2;
        const int i = ((int)blockIdx.x - 1) * 256 + threadIdx.x;
        float4* p1 = reinterpret_cast<float4*>(out1);
        float4* p2 = reinterpret_cast<float4*>(out2);
        float4 a = {0, 0, 0, 0}, b = {0, 0, 0, 0};
        if (i < n4) { a = p1[i]; b = p2[i]; }
        float ta = 0.0f, tb = 0.0f;
        const bool tail = (blockIdx.x == 1) && (threadIdx.x < (total & 3));
        const int tIdx = (n4 << 2) + threadIdx.x;
        if (tail) { ta = out1[tIdx]; tb = out2[tIdx]; }

        // spin until block 0 releases the scales (block 0 is in wave 1 and
        // never waits, so progress is guaranteed)
        while (atomicAdd(&g_flag, 0) == 0) { __nanosleep(40); }
        const float f1 = g_scale[0];
        const float f2 = g_scale[1];

        if (i < n4) {
            a.x *= f1; a.y *= f1; a.z *= f1; a.w *= f1;
            p1[i] = a;
            b.x *= f2; b.y *= f2; b.z *= f2; b.w *= f2;
            p2[i] = b;
        }
        if (tail) { out1[tIdx] = ta * f1; out2[tIdx] = tb * f2; }
        return;
    }

    // ---- momentum scatter update (independent of the scales) ----
    const int warp = threadIdx.x >> 5;
    const int lane = threadIdx.x & 31;
    const int b = ((int)blockIdx.x - 1 - normBlocks) * 8 + warp;
    if (b >= B) return;
    const int yb = y[b];
    for (int b2 = b + 1; b2 < B; ++b2)
        if (y[b2] == yb) return;            // last duplicate wins

    {
        const float4 mv = reinterpret_cast<const float4*>(m1 + (size_t)yb * 128)[lane];
        const float4 vv = reinterpret_cast<const float4*>(v1 + (size_t)b  * 128)[lane];
        float4 p = { 0.5f*(mv.x+vv.x), 0.5f*(mv.y+vv.y), 0.5f*(mv.z+vv.z), 0.5f*(mv.w+vv.w) };
        float ss = p.x*p.x + p.y*p.y + p.z*p.z + p.w*p.w;
        #pragma unroll
        for (int o = 16; o; o >>= 1) ss += __shfl_xor_sync(0xffffffffu, ss, o);
        const float inv = 1.0f / sqrtf(ss);
        p.x *= inv; p.y *= inv; p.z *= inv; p.w *= inv;
        reinterpret_cast<float4*>(om1 + (size_t)yb * 128)[lane] = p;
    }
    {
        const float4 mv = reinterpret_cast<const float4*>(m2 + (size_t)yb * 128)[lane];
        const float4 vv = reinterpret_cast<const float4*>(v2 + (size_t)b  * 128)[lane];
        float4 p = { 0.5f*(mv.x+vv.x), 0.5f*(mv.y+vv.y), 0.5f*(mv.z+vv.z), 0.5f*(mv.w+vv.w) };
        float ss = p.x*p.x + p.y*p.y + p.z*p.z + p.w*p.w;
        #pragma unroll
        for (int o = 16; o; o >>= 1) ss += __shfl_xor_sync(0xffffffffu, ss, o);
        const float inv = 1.0f / sqrtf(ss);
        p.x *= inv; p.y *= inv; p.z *= inv; p.w *= inv;
        reinterpret_cast<float4*>(om2 + (size_t)yb * 128)[lane] = p;
    }
}

extern "C" void kernel_launch(void* const* d_in, const int* in_sizes, int n_in,
                              void* d_out, int out_size)
{
    const float* v1  = (const float*)d_in[0];
    const float* v2  = (const float*)d_in[1];
    const float* m1  = (const float*)d_in[2];
    const float* m2  = (const float*)d_in[3];
    const int*   y   = (const int*)d_in[4];
    const int*   idx = (const int*)d_in[5];

    const int B = in_sizes[4];                 // 256
    const int D = in_sizes[0] / B;             // 128
    const size_t ND = (size_t)in_sizes[2];     // N*D
    const int KP1 = in_sizes[5] / B;           // 4097
    const int N = (int)(ND / (size_t)D);       // 1,000,000

    float* out  = (float*)d_out;
    float* out1 = out;
    float* out2 = out + (size_t)B * KP1;
    float* om1  = out + 2 * (size_t)B * KP1;
    float* om2  = om1 + ND;

    zero_kernel<<<1024, 256>>>(N);

    histogram_kernel<<<dim3((KP1 + 255) / 256, B), 256>>>(y, idx, KP1);

    fused_kernel<<<2048, 512>>>(m1, m2, v1, v2, om1, om2, out1, out2, N, KP1);

    const int total = B * KP1;
    const int normBlocks = ((total >> 2) + 255) / 256;
    const int updBlocks = (B + 7) / 8;
    epilogue_kernel<<<1 + normBlocks + updBlocks, 256>>>(
        out1, out2, total, (double)N,
        v1, v2, m1, m2, y, idx, KP1, om1, om2, B, normBlocks);
}

// round 16
// speedup vs baseline: 2.4717x; 2.4717x over previous
#include <cuda_runtime.h>
#include <cstddef>

// ---------------------------------------------------------------------------
// NCEAverageMultiview on GB300 — inverted-index formulation, 4-row stream.
// (round-14 structure; histogram with 4-way load batching)
//
// d_out (fp32): out_v1 [B*KP1] | out_v2 [B*KP1] | new_mem_v1 [N*D] | new_mem_v2 [N*D]
// ---------------------------------------------------------------------------

#define MAXN 1100000
#define CAP  8
#define OVF_CAP 65536

__device__ int    g_count[MAXN];
__device__ int    g_entries[MAXN * CAP];
__device__ int    g_ovf[OVF_CAP];
__device__ int    g_ovf_n;
__device__ double g_sum[2];
__device__ float  g_scale[2];

#define DOT4(p, a) ((p).x*(a).x + (p).y*(a).y + (p).z*(a).z + (p).w*(a).w)

__global__ void zero_kernel(int N) {
    const int n4 = N >> 2;
    const int i = blockIdx.x * blockDim.x + threadIdx.x;
    const int stride = gridDim.x * blockDim.x;
    int4* p = reinterpret_cast<int4*>(g_count);
    const int4 z = {0, 0, 0, 0};
    for (int j = i; j < n4; j += stride) p[j] = z;
    if (i == 0) {
        for (int j = n4 << 2; j < N; ++j) g_count[j] = 0;
        g_ovf_n = 0; g_sum[0] = 0.0; g_sum[1] = 0.0;
    }
}

// Build row -> (b,k) buckets. Entry encode: (b << 13) | k  (k <= 4096 < 8192).
// Each thread handles 4 k's: all idx loads issued first (MLP=4), then atomics.
__global__ void histogram_kernel(const int* __restrict__ y,
                                 const int* __restrict__ idx, int KP1) {
    const int k0 = (blockIdx.x * blockDim.x + threadIdx.x) * 4;
    const int b = blockIdx.y;
    if (k0 >= KP1) return;
    const int* __restrict__ idxb = idx + (size_t)b * KP1;

    int iv[4];
    #pragma unroll
    for (int t = 0; t < 4; ++t) {
        const int k = k0 + t;
        iv[t] = (k < KP1) ? ((k == 0) ? y[b] : __ldg(idxb + k)) : -1;
    }

    #pragma unroll
    for (int t = 0; t < 4; ++t) {
        const int k = k0 + t;
        if (iv[t] < 0) break;
        const int e = (b << 13) | k;
        const int slot = atomicAdd(&g_count[iv[t]], 1);
        if (slot < CAP) {
            g_entries[(size_t)iv[t] * CAP + slot] = e;
        } else {
            const int p = atomicAdd(&g_ovf_n, 1);
            if (p < OVF_CAP) g_ovf[p] = e;
        }
    }
}

// Streaming pass: warp handles 4 adjacent rows per iteration.
// 8 x 512B bank loads in flight; counts via one int4; all 4 rows' entries in
// ONE 128B transaction (lanes 0..31).
__global__ void __launch_bounds__(512) fused_kernel(
    const float* __restrict__ m1, const float* __restrict__ m2,
    const float* __restrict__ v1, const float* __restrict__ v2,
    float* __restrict__ om1, float* __restrict__ om2,
    float* __restrict__ out1, float* __restrict__ out2,
    int N, int KP1)
{
    __shared__ double sred1[16], sred2[16];
    const int lane = threadIdx.x & 31;
    const int warp = threadIdx.x >> 5;
    const int nWarps = gridDim.x * (blockDim.x >> 5);
    const int gw = blockIdx.x * (blockDim.x >> 5) + warp;
    const float invT = 1.0f / 0.07f;

    double acc1 = 0.0, acc2 = 0.0;
    const int Nquad = N & ~3;

    for (int r = gw * 4; r < Nquad; r += 4 * nWarps) {
        float4 x1[4], x2[4];
        #pragma unroll
        for (int q = 0; q < 4; ++q)
            x1[q] = __ldg(reinterpret_cast<const float4*>(m1 + (size_t)(r + q) * 128) + lane);
        #pragma unroll
        for (int q = 0; q < 4; ++q)
            x2[q] = __ldg(reinterpret_cast<const float4*>(m2 + (size_t)(r + q) * 128) + lane);

        const int4 cc = *reinterpret_cast<const int4*>(&g_count[r]);
        const int ev = g_entries[(size_t)r * CAP + lane];

        #pragma unroll
        for (int q = 0; q < 4; ++q)
            reinterpret_cast<float4*>(om1 + (size_t)(r + q) * 128)[lane] = x1[q];
        #pragma unroll
        for (int q = 0; q < 4; ++q)
            reinterpret_cast<float4*>(om2 + (size_t)(r + q) * 128)[lane] = x2[q];

        const int cArr[4] = { cc.x, cc.y, cc.z, cc.w };
        #pragma unroll
        for (int q = 0; q < 4; ++q) {
            int c = cArr[q];
            c = c < CAP ? c : CAP;
            for (int j = 0; j < c; ++j) {
                const int e = __shfl_sync(0xffffffffu, ev, q * CAP + j);
                const int b = e >> 13;
                const int k = e & 8191;
                const float4 a1 = __ldg(reinterpret_cast<const float4*>(v1 + (size_t)b * 128) + lane);
                const float4 a2 = __ldg(reinterpret_cast<const float4*>(v2 + (size_t)b * 128) + lane);
                // out_v1 = exp(<m2[r], v1[b]>/T);  out_v2 = exp(<m1[r], v2[b]>/T)
                float s1 = DOT4(x2[q], a1);
                float s2 = DOT4(x1[q], a2);
                #pragma unroll
                for (int o = 16; o; o >>= 1) {
                    s1 += __shfl_xor_sync(0xffffffffu, s1, o);
                    s2 += __shfl_xor_sync(0xffffffffu, s2, o);
                }
                if (lane == 0) {
                    const float e1 = __expf(s1 * invT);
                    const float e2 = __expf(s2 * invT);
                    out1[(size_t)b * KP1 + k] = e1;
                    out2[(size_t)b * KP1 + k] = e2;
                    acc1 += (double)e1;
                    acc2 += (double)e2;
                }
            }
        }
    }

    // tail rows (N not multiple of 4) handled by warp 0
    if (gw == 0) {
        for (int r = Nquad; r < N; ++r) {
            const float4 x1 = __ldg(reinterpret_cast<const float4*>(m1 + (size_t)r * 128) + lane);
            const float4 x2 = __ldg(reinterpret_cast<const float4*>(m2 + (size_t)r * 128) + lane);
            reinterpret_cast<float4*>(om1 + (size_t)r * 128)[lane] = x1;
            reinterpret_cast<float4*>(om2 + (size_t)r * 128)[lane] = x2;
            int c = g_count[r];
            const int ev = (lane < CAP) ? g_entries[(size_t)r * CAP + lane] : 0;
            c = c < CAP ? c : CAP;
            for (int j = 0; j < c; ++j) {
                const int e = __shfl_sync(0xffffffffu, ev, j);
                const int b = e >> 13;
                const int k = e & 8191;
                const float4 a1 = __ldg(reinterpret_cast<const float4*>(v1 + (size_t)b * 128) + lane);
                const float4 a2 = __ldg(reinterpret_cast<const float4*>(v2 + (size_t)b * 128) + lane);
                float s1 = DOT4(x2, a1);
                float s2 = DOT4(x1, a2);
                #pragma unroll
                for (int o = 16; o; o >>= 1) {
                    s1 += __shfl_xor_sync(0xffffffffu, s1, o);
                    s2 += __shfl_xor_sync(0xffffffffu, s2, o);
                }
                if (lane == 0) {
                    const float e1 = __expf(s1 * invT);
                    const float e2 = __expf(s2 * invT);
                    out1[(size_t)b * KP1 + k] = e1;
                    out2[(size_t)b * KP1 + k] = e2;
                    acc1 += (double)e1;
                    acc2 += (double)e2;
                }
            }
        }
    }

    if (lane == 0) { sred1[warp] = acc1; sred2[warp] = acc2; }
    __syncthreads();
    if (threadIdx.x == 0) {
        double t1 = 0.0, t2 = 0.0;
        #pragma unroll
        for (int j = 0; j < 16; ++j) { t1 += sred1[j]; t2 += sred2[j]; }
        atomicAdd(&g_sum[0], t1);
        atomicAdd(&g_sum[1], t2);
    }
}

// Overflow fix-up (expected ~0-2 entries) + scale computation, one launch.
__global__ void ovf_finalize_kernel(
    const float* __restrict__ m1, const float* __restrict__ m2,
    const float* __restrict__ v1, const float* __restrict__ v2,
    const int* __restrict__ y, const int* __restrict__ idx,
    float* __restrict__ out1, float* __restrict__ out2,
    int KP1, int total, double nOutput)
{
    const int lane = threadIdx.x;  // 32 threads, 1 block
    const float invT = 1.0f / 0.07f;
    int n = g_ovf_n;
    n = n < OVF_CAP ? n : OVF_CAP;
    double acc1 = 0.0, acc2 = 0.0;
    for (int t = 0; t < n; ++t) {
        const int e = g_ovf[t];
        const int b = e >> 13;
        const int k = e & 8191;
        const int i = (k == 0) ? y[b] : idx[(size_t)b * KP1 + k];
        const float4 x1 = reinterpret_cast<const float4*>(m1 + (size_t)i * 128)[lane];
        const float4 x2 = reinterpret_cast<const float4*>(m2 + (size_t)i * 128)[lane];
        const float4 a1 = reinterpret_cast<const float4*>(v1 + (size_t)b * 128)[lane];
        const float4 a2 = reinterpret_cast<const float4*>(v2 + (size_t)b * 128)[lane];
        float s1 = DOT4(x2, a1);
        float s2 = DOT4(x1, a2);
        #pragma unroll
        for (int o = 16; o; o >>= 1) {
            s1 += __shfl_xor_sync(0xffffffffu, s1, o);
            s2 += __shfl_xor_sync(0xffffffffu, s2, o);
        }
        if (lane == 0) {
            const float e1 = __expf(s1 * invT);
            const float e2 = __expf(s2 * invT);
            out1[(size_t)b * KP1 + k] = e1;
            out2[(size_t)b * KP1 + k] = e2;
            acc1 += (double)e1;
            acc2 += (double)e2;
        }
    }
    if (lane == 0) {
        const double s1 = g_sum[0] + acc1;
        const double s2 = g_sum[1] + acc2;
        const double cnt = (double)total;
        g_scale[0] = (float)(cnt / (s1 * nOutput));
        g_scale[1] = (float)(cnt / (s2 * nOutput));
    }
}

// Normalize outs (float4) + momentum scatter update (one warp per b).
__global__ void __launch_bounds__(256) epilogue_kernel(
    float* __restrict__ out1, float* __restrict__ out2, int total,
    const float* __restrict__ v1, const float* __restrict__ v2,
    const float* __restrict__ m1, const float* __restrict__ m2,
    const int* __restrict__ y,
    float* __restrict__ om1, float* __restrict__ om2,
    int B, int normBlocks)
{
    if ((int)blockIdx.x < normBlocks) {
        const float f1 = g_scale[0];
        const float f2 = g_scale[1];
        const int n4 = total >> 2;
        const int i = blockIdx.x * 256 + threadIdx.x;
        if (i < n4) {
            float4* p1 = reinterpret_cast<float4*>(out1);
            float4* p2 = reinterpret_cast<float4*>(out2);
            float4 a = p1[i];
            a.x *= f1; a.y *= f1; a.z *= f1; a.w *= f1;
            p1[i] = a;
            float4 b = p2[i];
            b.x *= f2; b.y *= f2; b.z *= f2; b.w *= f2;
            p2[i] = b;
        }
        if (blockIdx.x == 0 && threadIdx.x < (total & 3)) {
            const int t = (n4 << 2) + threadIdx.x;
            out1[t] *= f1;
            out2[t] *= f2;
        }
        return;
    }

    const int warp = threadIdx.x >> 5;
    const int lane = threadIdx.x & 31;
    const int b = ((int)blockIdx.x - normBlocks) * 8 + warp;
    if (b >= B) return;
    const int yb = y[b];
    for (int b2 = b + 1; b2 < B; ++b2)
        if (y[b2] == yb) return;            // last duplicate wins

    {
        const float4 mv = reinterpret_cast<const float4*>(m1 + (size_t)yb * 128)[lane];
        const float4 vv = reinterpret_cast<const float4*>(v1 + (size_t)b  * 128)[lane];
        float4 p = { 0.5f*(mv.x+vv.x), 0.5f*(mv.y+vv.y), 0.5f*(mv.z+vv.z), 0.5f*(mv.w+vv.w) };
        float ss = p.x*p.x + p.y*p.y + p.z*p.z + p.w*p.w;
        #pragma unroll
        for (int o = 16; o; o >>= 1) ss += __shfl_xor_sync(0xffffffffu, ss, o);
        const float inv = 1.0f / sqrtf(ss);
        p.x *= inv; p.y *= inv; p.z *= inv; p.w *= inv;
        reinterpret_cast<float4*>(om1 + (size_t)yb * 128)[lane] = p;
    }
    {
        const float4 mv = reinterpret_cast<const float4*>(m2 + (size_t)yb * 128)[lane];
        const float4 vv = reinterpret_cast<const float4*>(v2 + (size_t)b  * 128)[lane];
        float4 p = { 0.5f*(mv.x+vv.x), 0.5f*(mv.y+vv.y), 0.5f*(mv.z+vv.z), 0.5f*(mv.w+vv.w) };
        float ss = p.x*p.x + p.y*p.y + p.z*p.z + p.w*p.w;
        #pragma unroll
        for (int o = 16; o; o >>= 1) ss += __shfl_xor_sync(0xffffffffu, ss, o);
        const float inv = 1.0f / sqrtf(ss);
        p.x *= inv; p.y *= inv; p.z *= inv; p.w *= inv;
        reinterpret_cast<float4*>(om2 + (size_t)yb * 128)[lane] = p;
    }
}

extern "C" void kernel_launch(void* const* d_in, const int* in_sizes, int n_in,
                              void* d_out, int out_size)
{
    const float* v1  = (const float*)d_in[0];
    const float* v2  = (const float*)d_in[1];
    const float* m1  = (const float*)d_in[2];
    const float* m2  = (const float*)d_in[3];
    const int*   y   = (const int*)d_in[4];
    const int*   idx = (const int*)d_in[5];

    const int B = in_sizes[4];                 // 256
    const int D = in_sizes[0] / B;             // 128
    const size_t ND = (size_t)in_sizes[2];     // N*D
    const int KP1 = in_sizes[5] / B;           // 4097
    const int N = (int)(ND / (size_t)D);       // 1,000,000

    float* out  = (float*)d_out;
    float* out1 = out;
    float* out2 = out + (size_t)B * KP1;
    float* om1  = out + 2 * (size_t)B * KP1;
    float* om2  = om1 + ND;

    zero_kernel<<<1024, 256>>>(N);

    histogram_kernel<<<dim3((KP1 + 1023) / 1024, B), 256>>>(y, idx, KP1);

    fused_kernel<<<2048, 512>>>(m1, m2, v1, v2, om1, om2, out1, out2, N, KP1);

    const int total = B * KP1;
    ovf_finalize_kernel<<<1, 32>>>(m1, m2, v1, v2, y, idx, out1, out2,
                                   KP1, total, (double)N);

    const int normBlocks = ((total >> 2) + 255) / 256;
    const int updBlocks = (B + 7) / 8;
    epilogue_kernel<<<normBlocks + updBlocks, 256>>>(
        out1, out2, total,
        v1, v2, m1, m2, y, om1, om2, B, normBlocks);
}